// round 5
// baseline (speedup 1.0000x reference)
#include <cuda_runtime.h>

// Problem constants
#define B 32
#define S 2048
#define H 1024

// ---- split-softmax config ----
#define NSPLIT 16            // S-splits per batch -> 512 CTAs = 1 wave @ 4 CTA/SM
#define CH (S / NSPLIT)      // 128 rows per CTA
#define TROWS 8              // rows per register tile
#define NTILES (CH / TROWS)  // 16

// Scratch (no cudaMalloc allowed)
__device__ float  g_q[B * H];                        // 128 KB
__device__ float4 g_pacc[B * NSPLIT * (H / 4)];      // 2 MB
__device__ float  g_ml[B * NSPLIT * 2];
__device__ int    g_cnt[B];                          // zero-init; self-resetting

// ---------------------------------------------------------------------------
// Kernel 1: q[b,h] = sum_k h_t[b,k] * W[k,h]
// grid (4, B), 256 threads. Thread = (float4 col within 256-wide h-slice,
// k-quarter). h_t[b,:] staged in smem; smem reduce over 4 k-groups.
// ---------------------------------------------------------------------------
__global__ __launch_bounds__(256) void q_kernel(const float* __restrict__ h_t,
                                                const float* __restrict__ W)
{
    __shared__ float  hs[H];
    __shared__ float4 red[4][64];

    const int tid = threadIdx.x;
    const int hsl = blockIdx.x;          // h-slice 0..3 (256 floats each)
    const int b   = blockIdx.y;

    reinterpret_cast<float4*>(hs)[tid] =
        reinterpret_cast<const float4*>(h_t)[b * 256 + tid];
    __syncthreads();

    const int col = tid & 63;            // float4 col within slice
    const int kg  = tid >> 6;            // k-quarter 0..3

    const float4* wp = reinterpret_cast<const float4*>(W)
                     + (size_t)(kg * 256) * 256 + hsl * 64 + col;
    const float* hk = hs + kg * 256;

    float4 acc = make_float4(0.f, 0.f, 0.f, 0.f);
    #pragma unroll 8
    for (int kk = 0; kk < 256; kk++) {
        float4 w = wp[(size_t)kk * 256];
        float  h = hk[kk];
        acc.x = fmaf(h, w.x, acc.x);
        acc.y = fmaf(h, w.y, acc.y);
        acc.z = fmaf(h, w.z, acc.z);
        acc.w = fmaf(h, w.w, acc.w);
    }
    red[kg][col] = acc;
    __syncthreads();

    if (kg == 0) {
        #pragma unroll
        for (int w = 1; w < 4; w++) {
            float4 p = red[w][col];
            acc.x += p.x; acc.y += p.y; acc.z += p.z; acc.w += p.w;
        }
        reinterpret_cast<float4*>(g_q)[b * 256 + hsl * 64 + col] = acc;
    }
}

// ---------------------------------------------------------------------------
// Kernel 2: register-tile online-softmax split + fused combine.
// grid (NSPLIT, B), 256 threads. Last CTA per batch merges all splits and
// writes the final output (deterministic: fixed-order FP sums).
// ---------------------------------------------------------------------------
__global__ void __launch_bounds__(256, 4) split_kernel(const float* __restrict__ cntx,
                                                       const float* __restrict__ h_t,
                                                       const float* __restrict__ alpha,
                                                       const float* __restrict__ beta,
                                                       float* __restrict__ out)
{
    __shared__ float red[TROWS * 8];     // [row][warp]
    __shared__ float scores[TROWS];
    __shared__ int   is_last;

    const int tid  = threadIdx.x;
    const int b    = blockIdx.y;
    const int sp   = blockIdx.x;
    const int wid  = tid >> 5;
    const int lane = tid & 31;

    const float4* base4 = reinterpret_cast<const float4*>(
        cntx + ((size_t)b * S + (size_t)sp * CH) * H);

    const float4 qf = reinterpret_cast<const float4*>(g_q)[b * 256 + tid];

    float m = -1e30f, l = 0.f;
    float4 acc = make_float4(0.f, 0.f, 0.f, 0.f);

    for (int t = 0; t < NTILES; t++) {
        // 8 rows x 4 cols in registers (8 independent LDG.128, streaming)
        float4 v[TROWS];
        #pragma unroll
        for (int s = 0; s < TROWS; s++)
            v[s] = __ldcs(&base4[(size_t)(t * TROWS + s) * 256 + tid]);

        float p[TROWS];
        #pragma unroll
        for (int s = 0; s < TROWS; s++) {
            float ps;
            ps = v[s].x * qf.x;
            ps = fmaf(v[s].y, qf.y, ps);
            ps = fmaf(v[s].z, qf.z, ps);
            ps = fmaf(v[s].w, qf.w, ps);
            p[s] = ps;
        }
        #pragma unroll
        for (int s = 0; s < TROWS; s++) {
            #pragma unroll
            for (int off = 16; off > 0; off >>= 1)
                p[s] += __shfl_xor_sync(0xffffffffu, p[s], off);
        }
        if (lane == 0) {
            #pragma unroll
            for (int s = 0; s < TROWS; s++)
                red[s * 8 + wid] = p[s];
        }
        __syncthreads();
        if (wid == 0 && lane < TROWS) {
            float sum = 0.f;
            #pragma unroll
            for (int w = 0; w < 8; w++)
                sum += red[lane * 8 + w];
            scores[lane] = sum;
        }
        __syncthreads();

        float sc[TROWS];
        #pragma unroll
        for (int s = 0; s < TROWS; s++) sc[s] = scores[s];

        float mnew = m;
        #pragma unroll
        for (int s = 0; s < TROWS; s++) mnew = fmaxf(mnew, sc[s]);
        float corr = __expf(m - mnew);
        acc.x *= corr; acc.y *= corr; acc.z *= corr; acc.w *= corr;
        l *= corr;
        #pragma unroll
        for (int s = 0; s < TROWS; s++) {
            float w = __expf(sc[s] - mnew);
            l += w;
            acc.x = fmaf(w, v[s].x, acc.x);
            acc.y = fmaf(w, v[s].y, acc.y);
            acc.z = fmaf(w, v[s].z, acc.z);
            acc.w = fmaf(w, v[s].w, acc.w);
        }
        m = mnew;
        __syncthreads();   // protect red/scores for next tile
    }

    // publish partials
    g_pacc[((size_t)b * NSPLIT + sp) * 256 + tid] = acc;
    if (tid == 0) {
        g_ml[(b * NSPLIT + sp) * 2 + 0] = m;
        g_ml[(b * NSPLIT + sp) * 2 + 1] = l;
    }

    // arrival counter: last CTA of this batch does the merge
    __threadfence();
    __syncthreads();
    if (tid == 0) {
        int old = atomicAdd(&g_cnt[b], 1);
        is_last = (old == NSPLIT - 1);
    }
    __syncthreads();

    if (is_last) {
        __threadfence();   // acquire: see all other CTAs' partials

        float M = -1e30f;
        #pragma unroll
        for (int i = 0; i < NSPLIT; i++)
            M = fmaxf(M, g_ml[(b * NSPLIT + i) * 2 + 0]);

        float L = 0.f;
        float4 o = make_float4(0.f, 0.f, 0.f, 0.f);
        #pragma unroll
        for (int i = 0; i < NSPLIT; i++) {
            float mi = g_ml[(b * NSPLIT + i) * 2 + 0];
            float li = g_ml[(b * NSPLIT + i) * 2 + 1];
            float wi = __expf(mi - M);
            L += li * wi;
            float4 pv = g_pacc[((size_t)b * NSPLIT + i) * 256 + tid];
            o.x = fmaf(wi, pv.x, o.x);
            o.y = fmaf(wi, pv.y, o.y);
            o.z = fmaf(wi, pv.z, o.z);
            o.w = fmaf(wi, pv.w, o.w);
        }
        float a  = alpha[0];
        float bt = beta[0] / L;
        float4 hv = reinterpret_cast<const float4*>(h_t)[b * 256 + tid];
        float4 res;
        res.x = fmaf(a, hv.x, bt * o.x);
        res.y = fmaf(a, hv.y, bt * o.y);
        res.z = fmaf(a, hv.z, bt * o.z);
        res.w = fmaf(a, hv.w, bt * o.w);
        reinterpret_cast<float4*>(out)[b * 256 + tid] = res;

        if (tid == 0) g_cnt[b] = 0;   // reset for next graph replay
    }
}

// ---------------------------------------------------------------------------
extern "C" void kernel_launch(void* const* d_in, const int* in_sizes, int n_in,
                              void* d_out, int out_size)
{
    const float* h_t   = (const float*)d_in[0];
    const float* cntx  = (const float*)d_in[1];
    const float* W     = (const float*)d_in[2];
    const float* alpha = (const float*)d_in[3];
    const float* beta  = (const float*)d_in[4];
    float* out = (float*)d_out;

    q_kernel<<<dim3(4, B), 256>>>(h_t, W);
    split_kernel<<<dim3(NSPLIT, B), 256>>>(cntx, h_t, alpha, beta, out);
}

// round 7
// speedup vs baseline: 1.2661x; 1.2661x over previous
#include <cuda_runtime.h>

// Problem constants
#define B 32
#define S 2048
#define H 1024

// ---- split-softmax config ----
#define NSPLIT 16            // S-splits per batch
#define CH (S / NSPLIT)      // 128 rows per CTA
#define WARPS 4              // 128-thread CTAs
#define RPW (CH / WARPS)     // 32 rows per warp

// ---- q GEMV config ----
#define KSLICES 32
#define KCH (H / KSLICES)    // 32
#define BG 8

// Scratch (no cudaMalloc allowed)
__device__ float  g_qpart[KSLICES * B * H];          // 4 MB
__device__ float  g_q[B * H];                        // 128 KB
__device__ float4 g_pacc[B * NSPLIT * (H / 4)];      // 2 MB
__device__ float  g_ml[B * NSPLIT * 2];              // merged (M, L) per split

// ---------------------------------------------------------------------------
// Kernel 1: partial q[b,h] = sum_{k in slice} h_t[b,k] * W[k,h]
// grid (1, KSLICES=32, B/BG=4), 256 threads. Thread owns float4 of h,
// BG=8 batch accumulators -> W L2 traffic only 4x (16 MB).
// ---------------------------------------------------------------------------
__global__ __launch_bounds__(256) void qpart_kernel(const float* __restrict__ h_t,
                                                    const float* __restrict__ W)
{
    __shared__ float hs[BG][KCH];
    const int tid = threadIdx.x;
    const int k0  = blockIdx.y * KCH;
    const int bg  = blockIdx.z;

    {   // BG*KCH = 256 floats, one per thread
        int j  = tid >> 5;
        int kk = tid & 31;
        hs[j][kk] = h_t[(bg * BG + j) * H + k0 + kk];
    }
    __syncthreads();

    float4 acc[BG];
    #pragma unroll
    for (int j = 0; j < BG; j++) acc[j] = make_float4(0.f, 0.f, 0.f, 0.f);

    const float4* wp = reinterpret_cast<const float4*>(W) + (size_t)k0 * 256 + tid;
    #pragma unroll
    for (int kk = 0; kk < KCH; kk++) {
        float4 w = wp[(size_t)kk * 256];
        #pragma unroll
        for (int j = 0; j < BG; j++) {
            float h = hs[j][kk];
            acc[j].x = fmaf(h, w.x, acc[j].x);
            acc[j].y = fmaf(h, w.y, acc[j].y);
            acc[j].z = fmaf(h, w.z, acc[j].z);
            acc[j].w = fmaf(h, w.w, acc[j].w);
        }
    }
    float4* qp = reinterpret_cast<float4*>(g_qpart);
    #pragma unroll
    for (int j = 0; j < BG; j++)
        qp[((size_t)blockIdx.y * B + bg * BG + j) * 256 + tid] = acc[j];
}

// ---------------------------------------------------------------------------
// Kernel 1b: q = sum over KSLICES partials. grid (128), 256 threads.
// ---------------------------------------------------------------------------
__global__ __launch_bounds__(256) void qreduce_kernel()
{
    const int idx = blockIdx.x * 256 + threadIdx.x;
    float v = 0.f;
    #pragma unroll
    for (int p = 0; p < KSLICES; p++)
        v += g_qpart[(size_t)p * (B * H) + idx];
    g_q[idx] = v;
}

// ---------------------------------------------------------------------------
// Kernel 2: warp-autonomous split. grid (NSPLIT, B), 128 threads.
// Each warp owns RPW=32 full rows (lane spans H via 8 float4), processes
// 2 rows per iteration with private online softmax. NO barriers in loop.
// One CTA-end merge of the 4 warp states.
// ---------------------------------------------------------------------------
__global__ void __launch_bounds__(128, 4) split_kernel(const float* __restrict__ cntx)
{
    __shared__ float  q_s[H];              // 4 KB
    __shared__ float4 accbuf[WARPS][256];  // 16 KB
    __shared__ float  mlbuf[WARPS][2];

    const int tid  = threadIdx.x;
    const int wid  = tid >> 5;
    const int lane = tid & 31;
    const int b    = blockIdx.y;
    const int sp   = blockIdx.x;

    float4* q_s4 = reinterpret_cast<float4*>(q_s);
    q_s4[tid]       = reinterpret_cast<const float4*>(g_q)[b * 256 + tid];
    q_s4[tid + 128] = reinterpret_cast<const float4*>(g_q)[b * 256 + tid + 128];
    __syncthreads();

    const float4* base4 = reinterpret_cast<const float4*>(
        cntx + ((size_t)b * S + (size_t)sp * CH) * H);

    float m = -1e30f, l = 0.f;
    float4 acc[8];
    #pragma unroll
    for (int j = 0; j < 8; j++) acc[j] = make_float4(0.f, 0.f, 0.f, 0.f);

    for (int r = 0; r < RPW; r += 2) {
        const size_t row0 = (size_t)(wid * RPW + r) * 256;
        const size_t row1 = row0 + 256;

        float4 v0[8], v1[8];
        #pragma unroll
        for (int j = 0; j < 8; j++) v0[j] = __ldcs(&base4[row0 + j * 32 + lane]);
        #pragma unroll
        for (int j = 0; j < 8; j++) v1[j] = __ldcs(&base4[row1 + j * 32 + lane]);

        float d0 = 0.f, d1 = 0.f;
        #pragma unroll
        for (int j = 0; j < 8; j++) {
            float4 qv = q_s4[j * 32 + lane];
            d0 = fmaf(v0[j].x, qv.x, d0); d0 = fmaf(v0[j].y, qv.y, d0);
            d0 = fmaf(v0[j].z, qv.z, d0); d0 = fmaf(v0[j].w, qv.w, d0);
            d1 = fmaf(v1[j].x, qv.x, d1); d1 = fmaf(v1[j].y, qv.y, d1);
            d1 = fmaf(v1[j].z, qv.z, d1); d1 = fmaf(v1[j].w, qv.w, d1);
        }
        #pragma unroll
        for (int off = 16; off > 0; off >>= 1) {
            d0 += __shfl_xor_sync(0xffffffffu, d0, off);
            d1 += __shfl_xor_sync(0xffffffffu, d1, off);
        }

        float mnew = fmaxf(m, fmaxf(d0, d1));
        float corr = __expf(m - mnew);
        float e0   = __expf(d0 - mnew);
        float e1   = __expf(d1 - mnew);
        l = fmaf(l, corr, e0 + e1);
        #pragma unroll
        for (int j = 0; j < 8; j++) {
            acc[j].x = fmaf(acc[j].x, corr, fmaf(e0, v0[j].x, e1 * v1[j].x));
            acc[j].y = fmaf(acc[j].y, corr, fmaf(e0, v0[j].y, e1 * v1[j].y));
            acc[j].z = fmaf(acc[j].z, corr, fmaf(e0, v0[j].z, e1 * v1[j].z));
            acc[j].w = fmaf(acc[j].w, corr, fmaf(e0, v0[j].w, e1 * v1[j].w));
        }
        m = mnew;
    }

    // ---- CTA merge of 4 warp states ----
    if (lane == 0) { mlbuf[wid][0] = m; mlbuf[wid][1] = l; }
    __syncthreads();

    float M = -1e30f;
    #pragma unroll
    for (int w = 0; w < WARPS; w++) M = fmaxf(M, mlbuf[w][0]);
    float L = 0.f;
    #pragma unroll
    for (int w = 0; w < WARPS; w++) L += mlbuf[w][1] * __expf(mlbuf[w][0] - M);

    float wi = __expf(m - M);   // this warp's rescale
    #pragma unroll
    for (int j = 0; j < 8; j++) {
        float4 a = acc[j];
        a.x *= wi; a.y *= wi; a.z *= wi; a.w *= wi;
        accbuf[wid][j * 32 + lane] = a;
    }
    __syncthreads();

    // 128 threads cover 256 float4 columns (2 each), fixed-order sum
    #pragma unroll
    for (int c0 = 0; c0 < 2; c0++) {
        int c = tid + c0 * 128;
        float4 s = accbuf[0][c];
        #pragma unroll
        for (int w = 1; w < WARPS; w++) {
            float4 p = accbuf[w][c];
            s.x += p.x; s.y += p.y; s.z += p.z; s.w += p.w;
        }
        g_pacc[((size_t)b * NSPLIT + sp) * 256 + c] = s;
    }
    if (tid == 0) {
        g_ml[(b * NSPLIT + sp) * 2 + 0] = M;
        g_ml[(b * NSPLIT + sp) * 2 + 1] = L;
    }
}

// ---------------------------------------------------------------------------
// Kernel 3: combine. grid (16, B), 128 threads.
// CTA covers 16 float4 cols; 8 groups of 16 threads handle 2 splits each.
// ---------------------------------------------------------------------------
__global__ __launch_bounds__(128) void combine_kernel(const float* __restrict__ h_t,
                                                      const float* __restrict__ alpha,
                                                      const float* __restrict__ beta,
                                                      float* __restrict__ out)
{
    __shared__ float4 red[8][16];

    const int tid = threadIdx.x;
    const int c   = tid & 15;              // col within chunk
    const int grp = tid >> 4;              // 0..7
    const int col = blockIdx.x * 16 + c;   // float4 column 0..255
    const int b   = blockIdx.y;

    float M = -1e30f;
    #pragma unroll
    for (int i = 0; i < NSPLIT; i++)
        M = fmaxf(M, g_ml[(b * NSPLIT + i) * 2 + 0]);
    float L = 0.f;
    #pragma unroll
    for (int i = 0; i < NSPLIT; i++)
        L += g_ml[(b * NSPLIT + i) * 2 + 1] * __expf(g_ml[(b * NSPLIT + i) * 2 + 0] - M);

    float4 o = make_float4(0.f, 0.f, 0.f, 0.f);
    #pragma unroll
    for (int j = 0; j < 2; j++) {
        int i = grp * 2 + j;
        float wi = __expf(g_ml[(b * NSPLIT + i) * 2 + 0] - M);
        float4 p = g_pacc[((size_t)b * NSPLIT + i) * 256 + col];
        o.x = fmaf(wi, p.x, o.x);
        o.y = fmaf(wi, p.y, o.y);
        o.z = fmaf(wi, p.z, o.z);
        o.w = fmaf(wi, p.w, o.w);
    }
    red[grp][c] = o;
    __syncthreads();

    if (grp == 0) {
        #pragma unroll
        for (int w = 1; w < 8; w++) {
            float4 p = red[w][c];
            o.x += p.x; o.y += p.y; o.z += p.z; o.w += p.w;
        }
        float a  = alpha[0];
        float bt = beta[0] / L;
        float4 hv = reinterpret_cast<const float4*>(h_t)[b * 256 + col];
        float4 res;
        res.x = fmaf(a, hv.x, bt * o.x);
        res.y = fmaf(a, hv.y, bt * o.y);
        res.z = fmaf(a, hv.z, bt * o.z);
        res.w = fmaf(a, hv.w, bt * o.w);
        reinterpret_cast<float4*>(out)[b * 256 + col] = res;
    }
}

// ---------------------------------------------------------------------------
extern "C" void kernel_launch(void* const* d_in, const int* in_sizes, int n_in,
                              void* d_out, int out_size)
{
    const float* h_t   = (const float*)d_in[0];
    const float* cntx  = (const float*)d_in[1];
    const float* W     = (const float*)d_in[2];
    const float* alpha = (const float*)d_in[3];
    const float* beta  = (const float*)d_in[4];
    float* out = (float*)d_out;

    qpart_kernel<<<dim3(1, KSLICES, B / BG), 256>>>(h_t, W);
    qreduce_kernel<<<B * H / 256, 256>>>();
    split_kernel<<<dim3(NSPLIT, B), 128>>>(cntx);
    combine_kernel<<<dim3(16, B), 128>>>(h_t, alpha, beta, out);
}